// round 15
// baseline (speedup 1.0000x reference)
#include <cuda_runtime.h>
#include <cuda_bf16.h>
#include <cuda_fp16.h>
#include <cstdint>

// ---------------------------------------------------------------------------
// Problem dims (fixed by the dataset)
// ---------------------------------------------------------------------------
#define D_     2048
#define K_     2048
#define NTOT   6144            // 3*D
#define M_     8192            // 4*2048
#define R_     8

#define KC        64           // k-elems per chunk (128B fp16 rows, SW128)
#define NKC       32           // K_/KC
#define MHALVES   64           // M_/128
#define NHALVES   48           // NTOT/128
#define TILE_BYTES  16384      // one 128x64 fp16 tile (SW128 image)
#define STAGES    3
#define STAGE_BYTES 32768      // A (16K) + B (16K)
#define SMEM_REQ  (STAGES * STAGE_BYTES + 64 + 1024)  // stages + mbarriers + align

// fp16 blobs, stored as byte-exact SW128 tile images:
// blob[half*32 + kc] = 16KB tile; byte (r, c) at sw128(r*128 + c*2)
__device__ __align__(128) unsigned char g_X[(size_t)MHALVES * NKC * TILE_BYTES]; // 32 MB
__device__ __align__(128) unsigned char g_W[(size_t)NHALVES * NKC * TILE_BYTES]; // 24 MB

// ---------------------------------------------------------------------------
// PTX helpers (baseline sm_80/90 features only — all verified non-erroring
// in the R3 ptxas log for target sm_103)
// ---------------------------------------------------------------------------
__device__ __forceinline__ uint32_t smem_u32(const void* p) {
    uint32_t a;
    asm("{ .reg .u64 t; cvta.to.shared.u64 t, %1; cvt.u32.u64 %0, t; }" : "=r"(a) : "l"(p));
    return a;
}
#define CP_ASYNC16(s, g) \
    asm volatile("cp.async.cg.shared.global [%0], [%1], 16;" :: "r"(s), "l"(g) : "memory")

#define MBAR_INIT(addr, cnt) \
    asm volatile("mbarrier.init.shared.b64 [%0], %1;" :: "r"(addr), "r"(cnt) : "memory")

#define MBAR_ARRIVE(addr) \
    asm volatile("mbarrier.arrive.shared.b64 _, [%0];" :: "r"(addr) : "memory")

#define CPASYNC_MBAR_ARRIVE(addr) \
    asm volatile("cp.async.mbarrier.arrive.noinc.shared.b64 [%0];" :: "r"(addr) : "memory")

#define MBAR_WAIT(addr, parity) do {                                              \
    asm volatile("{\n\t.reg .pred P1;\n\t"                                        \
        "W_%=:\n\t"                                                               \
        "mbarrier.try_wait.parity.acquire.cta.shared::cta.b64 P1, [%0], %1, 0x989680;\n\t" \
        "@P1 bra.uni D_%=;\n\t"                                                   \
        "bra.uni W_%=;\n\t"                                                       \
        "D_%=:\n\t}"                                                              \
        :: "r"(addr), "r"(parity) : "memory");                                    \
} while (0)

#define LDSM_X4(r0, r1, r2, r3, a) \
    asm volatile("ldmatrix.sync.aligned.m8n8.x4.shared.b16 {%0,%1,%2,%3}, [%4];" \
                 : "=r"(r0), "=r"(r1), "=r"(r2), "=r"(r3) : "r"(a))

#define MMA_F16(d, a0, a1, a2, a3, b0, b1) \
    asm volatile("mma.sync.aligned.m16n8k16.row.col.f32.f16.f16.f32 " \
                 "{%0,%1,%2,%3}, {%4,%5,%6,%7}, {%8,%9}, {%0,%1,%2,%3};" \
                 : "+f"((d)[0]), "+f"((d)[1]), "+f"((d)[2]), "+f"((d)[3]) \
                 : "r"(a0), "r"(a1), "r"(a2), "r"(a3), "r"(b0), "r"(b1))

__device__ __forceinline__ uint32_t swz(uint32_t off) { return off ^ ((off >> 3) & 0x70u); }

// ---------------------------------------------------------------------------
// Convert kernels: fp32 -> fp16 in pre-swizzled blob layout.
// ---------------------------------------------------------------------------
__device__ __forceinline__ void cvt8_store(const float* xs, unsigned char* blobbase,
                                           unsigned m_in_half, unsigned k_in_chunk) {
    union { unsigned short s[8]; uint4 v; } h;
#pragma unroll
    for (int j = 0; j < 8; j++) h.s[j] = __half_as_ushort(__float2half_rn(xs[j]));
    unsigned off = (m_in_half << 7) | (k_in_chunk << 1);
    *(uint4*)(blobbase + swz(off)) = h.v;
}

__global__ void __launch_bounds__(256) convX(const float* __restrict__ X) {
    unsigned idx = blockIdx.x * 256u + threadIdx.x;
    unsigned m  = idx >> 8;
    unsigned k0 = (idx & 255u) << 3;
    const float4* src = (const float4*)(X + (size_t)m * K_ + k0);
    float4 v0 = src[0], v1 = src[1];
    float xs[8] = {v0.x, v0.y, v0.z, v0.w, v1.x, v1.y, v1.z, v1.w};
    size_t blob = ((size_t)(m >> 7) * NKC + (k0 >> 6)) * TILE_BYTES;
    cvt8_store(xs, g_X + blob, m & 127u, k0 & 63u);
}

__global__ void __launch_bounds__(256) convW(const float* __restrict__ W,
                                             const float* __restrict__ A1,
                                             const float* __restrict__ B1,
                                             const float* __restrict__ A2,
                                             const float* __restrict__ B2) {
    unsigned idx = blockIdx.x * 256u + threadIdx.x;
    unsigned n  = idx >> 8;
    unsigned k0 = (idx & 255u) << 3;
    const float4* src = (const float4*)(W + (size_t)n * K_ + k0);
    float4 v0 = src[0], v1 = src[1];
    float xs[8] = {v0.x, v0.y, v0.z, v0.w, v1.x, v1.y, v1.z, v1.w};
    if (n >= D_) {
        const float* A;
        const float* Brow;
        if (n < 2 * D_) { A = A1; Brow = B1 + (size_t)(n - D_) * R_; }
        else            { A = A2; Brow = B2 + (size_t)(n - 2 * D_) * R_; }
#pragma unroll
        for (int r = 0; r < R_; r++) {
            float bv = Brow[r];
            const float* Ar = A + (size_t)r * K_ + k0;
#pragma unroll
            for (int j = 0; j < 8; j++) xs[j] = fmaf(bv, Ar[j], xs[j]);
        }
    }
    size_t blob = ((size_t)(n >> 7) * NKC + (k0 >> 6)) * TILE_BYTES;
    cvt8_store(xs, g_W + blob, n & 127u, k0 & 63u);
}

// ---------------------------------------------------------------------------
// GEMM: 128x128 CTA tile, 4 warps (2m x 2n), warp tile 64x64, BK=64,
// 3-stage pipeline synced by per-stage mbarriers (NO __syncthreads, NO
// commit_group) — warps free-run across chunk boundaries. 2 CTAs/SM.
// fp16 HMMA (m16n8k16), fp32 accumulate.
// ---------------------------------------------------------------------------
__device__ __forceinline__ void issue_chunk(uint32_t st, const unsigned char* ga,
                                            const unsigned char* gb, int tid) {
#pragma unroll
    for (int i = 0; i < 8; i++) {
        uint32_t off = (uint32_t)(i * 128 + tid) * 16u;
        CP_ASYNC16(st + off,          ga + off);
        CP_ASYNC16(st + 16384u + off, gb + off);
    }
}

__global__ void __launch_bounds__(128, 2)
gemm_hmma(const float* __restrict__ bias, float* __restrict__ out) {
    extern __shared__ __align__(16) unsigned char smem_raw[];
    const uint32_t base = (smem_u32(smem_raw) + 1023u) & ~1023u;
    const uint32_t fullb  = base + STAGES * STAGE_BYTES;        // 3 x 8B
    const uint32_t emptyb = fullb + 24;                         // 3 x 8B

    const int tid  = threadIdx.x;
    const int wid  = tid >> 5;
    const int lane = tid & 31;
    const int wm   = wid >> 1;          // 0..1  (64-row slab)
    const int wn   = wid & 1;           // 0..1  (64-col slab)

    const int bn = blockIdx.x;          // 0..47
    const int bm = blockIdx.y;          // 0..63

    const unsigned char* Ab = g_X + (size_t)bm * NKC * TILE_BYTES;
    const unsigned char* Bb = g_W + (size_t)bn * NKC * TILE_BYTES;

    if (tid == 0) {
#pragma unroll
        for (int s = 0; s < STAGES; s++) {
            MBAR_INIT(fullb  + s * 8, 128u);   // 128 threads' cp.async arrives
            MBAR_INIT(emptyb + s * 8, 128u);   // 128 threads' consume arrives
        }
    }
    __syncthreads();    // barriers initialized (only CTA-wide sync in kernel)

    // Per-lane ldmatrix base byte offsets (pre-swizzle) within a tile image.
    const uint32_t a_base = (uint32_t)((wm * 64 + (lane & 15)) * 128 + ((lane >> 4) & 1) * 16);
    const uint32_t b_base = (uint32_t)((wn * 64 + (lane & 7) + ((lane >> 4) << 3)) * 128
                                       + ((lane >> 3) & 1) * 16);

    float acc[4][8][4];
#pragma unroll
    for (int i = 0; i < 4; i++)
#pragma unroll
        for (int j = 0; j < 8; j++)
#pragma unroll
            for (int q = 0; q < 4; q++) acc[i][j][q] = 0.0f;

    // Prologue: every thread issues its quarter of chunks 0,1 and signals
    // the stage's full barrier via async arrive (fires when data lands).
#pragma unroll
    for (int s = 0; s < STAGES - 1; s++) {
        issue_chunk(base + (uint32_t)s * STAGE_BYTES,
                    Ab + (size_t)s * TILE_BYTES,
                    Bb + (size_t)s * TILE_BYTES, tid);
        CPASYNC_MBAR_ARRIVE(fullb + s * 8);
    }

    for (int kc = 0; kc < NKC; kc++) {
        const int s = kc % STAGES;
        const int t = kc / STAGES;

        // 1. wait for this chunk's data (acquire)
        MBAR_WAIT(fullb + s * 8, t & 1);

        const uint32_t st = base + (uint32_t)s * STAGE_BYTES;
        const uint32_t As = st;
        const uint32_t Bs = st + 16384u;

        // 2. compute
#pragma unroll
        for (int kk = 0; kk < 4; kk++) {
            const uint32_t kb = (uint32_t)kk * 32u;
            uint32_t a[16], b[16];
#pragma unroll
            for (int i = 0; i < 4; i++) {
                uint32_t o = swz(a_base + (uint32_t)i * 2048u + kb);
                LDSM_X4(a[4*i+0], a[4*i+1], a[4*i+2], a[4*i+3], As + o);
            }
#pragma unroll
            for (int g = 0; g < 4; g++) {
                uint32_t o = swz(b_base + (uint32_t)g * 2048u + kb);
                LDSM_X4(b[4*g+0], b[4*g+1], b[4*g+2], b[4*g+3], Bs + o);
            }
#pragma unroll
            for (int i = 0; i < 4; i++) {
#pragma unroll
                for (int j = 0; j < 8; j++) {
                    const int g = j >> 1, h = (j & 1) << 1;
                    MMA_F16(acc[i][j], a[4*i+0], a[4*i+1], a[4*i+2], a[4*i+3],
                            b[4*g+h], b[4*g+h+1]);
                }
            }
        }

        // 3. release this stage
        MBAR_ARRIVE(emptyb + s * 8);

        // 4+5. prefetch chunk kc+2 into stage (kc+2)%3 (off critical path)
        if (kc + 2 < NKC) {
            const int s2 = (kc + 2) % STAGES;
            // stage 2 starts free (fresh barrier passes at parity 1);
            // stages 0,1 are first freed by consumption (parity 0 first).
            const int ep = (t ^ ((s2 == 2) ? 1 : 0)) & 1;
            MBAR_WAIT(emptyb + s2 * 8, ep);
            issue_chunk(base + (uint32_t)s2 * STAGE_BYTES,
                        Ab + (size_t)(kc + 2) * TILE_BYTES,
                        Bb + (size_t)(kc + 2) * TILE_BYTES, tid);
            CPASYNC_MBAR_ARRIVE(fullb + s2 * 8);
        }
    }

    // ---- epilogue: bias + store ----
    const int m0 = bm * 128 + wm * 64;
    const int n0 = bn * 128 + wn * 64;
    const int r  = lane >> 2;
    const int cp = (lane & 3) * 2;

#pragma unroll
    for (int j = 0; j < 8; j++) {
        const int n = n0 + j * 8 + cp;
        const float2 bv = *(const float2*)(bias + n);
#pragma unroll
        for (int i = 0; i < 4; i++) {
            const int row0 = m0 + i * 16 + r;
            float2 o0 = make_float2(acc[i][j][0] + bv.x, acc[i][j][1] + bv.y);
            float2 o1 = make_float2(acc[i][j][2] + bv.x, acc[i][j][3] + bv.y);
            *(float2*)(out + (size_t)row0 * NTOT + n)       = o0;
            *(float2*)(out + (size_t)(row0 + 8) * NTOT + n) = o1;
        }
    }
}

// ---------------------------------------------------------------------------
extern "C" void kernel_launch(void* const* d_in, const int* in_sizes, int n_in,
                              void* d_out, int out_size) {
    const float* x  = (const float*)d_in[0];
    const float* W  = (const float*)d_in[1];
    const float* b  = (const float*)d_in[2];
    const float* A1 = (const float*)d_in[3];
    const float* B1 = (const float*)d_in[4];
    const float* A2 = (const float*)d_in[5];
    const float* B2 = (const float*)d_in[6];
    float* out = (float*)d_out;

    convX<<<M_ * (K_ / 8) / 256, 256>>>(x);
    convW<<<NTOT * (K_ / 8) / 256, 256>>>(W, A1, B1, A2, B2);

    cudaFuncSetAttribute(gemm_hmma, cudaFuncAttributeMaxDynamicSharedMemorySize, SMEM_REQ);
    dim3 grid(NTOT / 128, M_ / 128);   // (48, 64)
    gemm_hmma<<<grid, 128, SMEM_REQ>>>(b, out);
}

// round 16
// speedup vs baseline: 1.4052x; 1.4052x over previous
#include <cuda_runtime.h>
#include <cuda_bf16.h>
#include <cuda_fp16.h>
#include <cstdint>

// ---------------------------------------------------------------------------
// Problem dims (fixed by the dataset)
// ---------------------------------------------------------------------------
#define D_     2048
#define K_     2048
#define NTOT   6144            // 3*D
#define M_     8192            // 4*2048
#define R_     8

#define KC        64           // k-elems per chunk (128B fp16 rows, SW128)
#define NKC       32           // K_/KC
#define MHALVES   64           // M_/128
#define NHALVES   48           // NTOT/128
#define TILE_BYTES  16384      // one 128x64 fp16 tile (SW128 image)
#define STAGES    3
#define STAGE_BYTES 32768      // A (16K) + B (16K)
#define SMEM_REQ  (STAGES * STAGE_BYTES + 1024)   // 99328 -> 2 CTAs/SM

#define NTILES    (MHALVES * NHALVES)   // 3072 output tiles (128x128)
#define NCTAS     296                   // 2 per SM x 148 SMs, persistent

// fp16 blobs, stored as byte-exact SW128 tile images:
// blob[half*32 + kc] = 16KB tile; byte (r, c) at sw128(r*128 + c*2)
__device__ __align__(128) unsigned char g_X[(size_t)MHALVES * NKC * TILE_BYTES]; // 32 MB
__device__ __align__(128) unsigned char g_W[(size_t)NHALVES * NKC * TILE_BYTES]; // 24 MB

// ---------------------------------------------------------------------------
// PTX helpers (baseline sm_80/90 features only)
// ---------------------------------------------------------------------------
__device__ __forceinline__ uint32_t smem_u32(const void* p) {
    uint32_t a;
    asm("{ .reg .u64 t; cvta.to.shared.u64 t, %1; cvt.u32.u64 %0, t; }" : "=r"(a) : "l"(p));
    return a;
}
#define CP_ASYNC16(s, g) \
    asm volatile("cp.async.cg.shared.global [%0], [%1], 16;" :: "r"(s), "l"(g) : "memory")
#define CP_COMMIT() asm volatile("cp.async.commit_group;" ::: "memory")
#define CP_WAIT(n)  asm volatile("cp.async.wait_group %0;" :: "n"(n) : "memory")

#define LDSM_X4(r0, r1, r2, r3, a) \
    asm volatile("ldmatrix.sync.aligned.m8n8.x4.shared.b16 {%0,%1,%2,%3}, [%4];" \
                 : "=r"(r0), "=r"(r1), "=r"(r2), "=r"(r3) : "r"(a))

#define MMA_F16(d, a0, a1, a2, a3, b0, b1) \
    asm volatile("mma.sync.aligned.m16n8k16.row.col.f32.f16.f16.f32 " \
                 "{%0,%1,%2,%3}, {%4,%5,%6,%7}, {%8,%9}, {%0,%1,%2,%3};" \
                 : "+f"((d)[0]), "+f"((d)[1]), "+f"((d)[2]), "+f"((d)[3]) \
                 : "r"(a0), "r"(a1), "r"(a2), "r"(a3), "r"(b0), "r"(b1))

__device__ __forceinline__ uint32_t swz(uint32_t off) { return off ^ ((off >> 3) & 0x70u); }

// ---------------------------------------------------------------------------
// Convert kernels: fp32 -> fp16 in pre-swizzled blob layout.
// ---------------------------------------------------------------------------
__device__ __forceinline__ void cvt8_store(const float* xs, unsigned char* blobbase,
                                           unsigned m_in_half, unsigned k_in_chunk) {
    union { unsigned short s[8]; uint4 v; } h;
#pragma unroll
    for (int j = 0; j < 8; j++) h.s[j] = __half_as_ushort(__float2half_rn(xs[j]));
    unsigned off = (m_in_half << 7) | (k_in_chunk << 1);
    *(uint4*)(blobbase + swz(off)) = h.v;
}

__global__ void __launch_bounds__(256) convX(const float* __restrict__ X) {
    unsigned idx = blockIdx.x * 256u + threadIdx.x;
    unsigned m  = idx >> 8;
    unsigned k0 = (idx & 255u) << 3;
    const float4* src = (const float4*)(X + (size_t)m * K_ + k0);
    float4 v0 = src[0], v1 = src[1];
    float xs[8] = {v0.x, v0.y, v0.z, v0.w, v1.x, v1.y, v1.z, v1.w};
    size_t blob = ((size_t)(m >> 7) * NKC + (k0 >> 6)) * TILE_BYTES;
    cvt8_store(xs, g_X + blob, m & 127u, k0 & 63u);
}

__global__ void __launch_bounds__(256) convW(const float* __restrict__ W,
                                             const float* __restrict__ A1,
                                             const float* __restrict__ B1,
                                             const float* __restrict__ A2,
                                             const float* __restrict__ B2) {
    unsigned idx = blockIdx.x * 256u + threadIdx.x;
    unsigned n  = idx >> 8;
    unsigned k0 = (idx & 255u) << 3;
    const float4* src = (const float4*)(W + (size_t)n * K_ + k0);
    float4 v0 = src[0], v1 = src[1];
    float xs[8] = {v0.x, v0.y, v0.z, v0.w, v1.x, v1.y, v1.z, v1.w};
    if (n >= D_) {
        const float* A;
        const float* Brow;
        if (n < 2 * D_) { A = A1; Brow = B1 + (size_t)(n - D_) * R_; }
        else            { A = A2; Brow = B2 + (size_t)(n - 2 * D_) * R_; }
#pragma unroll
        for (int r = 0; r < R_; r++) {
            float bv = Brow[r];
            const float* Ar = A + (size_t)r * K_ + k0;
#pragma unroll
            for (int j = 0; j < 8; j++) xs[j] = fmaf(bv, Ar[j], xs[j]);
        }
    }
    size_t blob = ((size_t)(n >> 7) * NKC + (k0 >> 6)) * TILE_BYTES;
    cvt8_store(xs, g_W + blob, n & 127u, k0 & 63u);
}

// ---------------------------------------------------------------------------
// Persistent GEMM: 296 CTAs, each loops over ~10 output tiles (128x128).
// Per tile: 4 warps (2m x 2n), warp tile 64x64, BK=64, fp16 HMMA.
// The 3-stage cp.async pipeline runs CONTINUOUSLY across tile boundaries:
// stage = global_chunk % 3; prefetch of chunk g+2 may target the next tile.
// Mainloop body identical to the best-measured R8 kernel.
// ---------------------------------------------------------------------------
__device__ __forceinline__ void issue_chunk(uint32_t st, const unsigned char* ga,
                                            const unsigned char* gb, int tid) {
#pragma unroll
    for (int i = 0; i < 8; i++) {
        uint32_t off = (uint32_t)(i * 128 + tid) * 16u;
        CP_ASYNC16(st + off,          ga + off);
        CP_ASYNC16(st + 16384u + off, gb + off);
    }
}

// tile index t (0..NTILES-1) -> blob base pointers (same mapping as R8 grid)
__device__ __forceinline__ const unsigned char* tileA(int t) {
    return g_X + (size_t)(t / NHALVES) * NKC * TILE_BYTES;
}
__device__ __forceinline__ const unsigned char* tileB(int t) {
    return g_W + (size_t)(t % NHALVES) * NKC * TILE_BYTES;
}

__global__ void __launch_bounds__(128, 2)
gemm_hmma(const float* __restrict__ bias, float* __restrict__ out) {
    extern __shared__ __align__(16) unsigned char smem_raw[];
    const uint32_t base = (smem_u32(smem_raw) + 1023u) & ~1023u;

    const int tid  = threadIdx.x;
    const int wid  = tid >> 5;
    const int lane = tid & 31;
    const int wm   = wid >> 1;          // 0..1  (64-row slab)
    const int wn   = wid & 1;           // 0..1  (64-col slab)
    const int bid  = blockIdx.x;        // 0..295

    const int ntiles = (NTILES - bid + NCTAS - 1) / NCTAS;   // 10 or 11
    if (ntiles <= 0) return;

    // Per-lane ldmatrix base byte offsets (pre-swizzle) within a tile image.
    const uint32_t a_base = (uint32_t)((wm * 64 + (lane & 15)) * 128 + ((lane >> 4) & 1) * 16);
    const uint32_t b_base = (uint32_t)((wn * 64 + (lane & 7) + ((lane >> 4) << 3)) * 128
                                       + ((lane >> 3) & 1) * 16);

    // Prologue: prefetch global chunks 0,1 (tile 0 of my list)
    {
        const unsigned char* Ab0 = tileA(bid);
        const unsigned char* Bb0 = tileB(bid);
#pragma unroll
        for (int s = 0; s < 2; s++) {
            issue_chunk(base + (uint32_t)s * STAGE_BYTES,
                        Ab0 + (size_t)s * TILE_BYTES,
                        Bb0 + (size_t)s * TILE_BYTES, tid);
            CP_COMMIT();
        }
    }

    for (int i = 0; i < ntiles; i++) {
        const int t = bid + i * NCTAS;
        const unsigned char* Ab = tileA(t);
        const unsigned char* Bb = tileB(t);

        float acc[4][8][4];
#pragma unroll
        for (int ii = 0; ii < 4; ii++)
#pragma unroll
            for (int j = 0; j < 8; j++)
#pragma unroll
                for (int q = 0; q < 4; q++) acc[ii][j][q] = 0.0f;

        for (int kc = 0; kc < NKC; kc++) {
            const int g = i * NKC + kc;            // global chunk counter
            CP_WAIT(1);                            // chunk g resident
            __syncthreads();                       // stage (g+2)%3 free to overwrite

            // Prefetch global chunk g+2 (may belong to the next tile)
            {
                const int gp = g + 2;
                const int ip = gp >> 5;            // tile list index
                const int kp = gp & 31;            // chunk within that tile
                if (ip < ntiles) {
                    const int tp = bid + ip * NCTAS;
                    issue_chunk(base + (uint32_t)(gp % STAGES) * STAGE_BYTES,
                                tileA(tp) + (size_t)kp * TILE_BYTES,
                                tileB(tp) + (size_t)kp * TILE_BYTES, tid);
                }
            }
            CP_COMMIT();                           // uniform group count

            const uint32_t st = base + (uint32_t)(g % STAGES) * STAGE_BYTES;
            const uint32_t As = st;
            const uint32_t Bs = st + 16384u;

#pragma unroll
            for (int kk = 0; kk < 4; kk++) {
                const uint32_t kb = (uint32_t)kk * 32u;
                uint32_t a[16], b[16];
#pragma unroll
                for (int ii = 0; ii < 4; ii++) {
                    uint32_t o = swz(a_base + (uint32_t)ii * 2048u + kb);
                    LDSM_X4(a[4*ii+0], a[4*ii+1], a[4*ii+2], a[4*ii+3], As + o);
                }
#pragma unroll
                for (int gg = 0; gg < 4; gg++) {
                    uint32_t o = swz(b_base + (uint32_t)gg * 2048u + kb);
                    LDSM_X4(b[4*gg+0], b[4*gg+1], b[4*gg+2], b[4*gg+3], Bs + o);
                }
#pragma unroll
                for (int ii = 0; ii < 4; ii++) {
#pragma unroll
                    for (int j = 0; j < 8; j++) {
                        const int gg = j >> 1, h = (j & 1) << 1;
                        MMA_F16(acc[ii][j], a[4*ii+0], a[4*ii+1], a[4*ii+2], a[4*ii+3],
                                b[4*gg+h], b[4*gg+h+1]);
                    }
                }
            }
        }

        // ---- epilogue for tile t (overlaps with in-flight prefetch) ----
        const int bm = t / NHALVES;
        const int bn = t % NHALVES;
        const int m0 = bm * 128 + wm * 64;
        const int n0 = bn * 128 + wn * 64;
        const int r  = lane >> 2;
        const int cp = (lane & 3) * 2;

#pragma unroll
        for (int j = 0; j < 8; j++) {
            const int n = n0 + j * 8 + cp;
            const float2 bv = *(const float2*)(bias + n);
#pragma unroll
            for (int ii = 0; ii < 4; ii++) {
                const int row0 = m0 + ii * 16 + r;
                float2 o0 = make_float2(acc[ii][j][0] + bv.x, acc[ii][j][1] + bv.y);
                float2 o1 = make_float2(acc[ii][j][2] + bv.x, acc[ii][j][3] + bv.y);
                *(float2*)(out + (size_t)row0 * NTOT + n)       = o0;
                *(float2*)(out + (size_t)(row0 + 8) * NTOT + n) = o1;
            }
        }
    }
}

// ---------------------------------------------------------------------------
extern "C" void kernel_launch(void* const* d_in, const int* in_sizes, int n_in,
                              void* d_out, int out_size) {
    const float* x  = (const float*)d_in[0];
    const float* W  = (const float*)d_in[1];
    const float* b  = (const float*)d_in[2];
    const float* A1 = (const float*)d_in[3];
    const float* B1 = (const float*)d_in[4];
    const float* A2 = (const float*)d_in[5];
    const float* B2 = (const float*)d_in[6];
    float* out = (float*)d_out;

    convX<<<M_ * (K_ / 8) / 256, 256>>>(x);
    convW<<<NTOT * (K_ / 8) / 256, 256>>>(W, A1, B1, A2, B2);

    cudaFuncSetAttribute(gemm_hmma, cudaFuncAttributeMaxDynamicSharedMemorySize, SMEM_REQ);
    gemm_hmma<<<NCTAS, 128, SMEM_REQ>>>(b, out);
}